// round 1
// baseline (speedup 1.0000x reference)
#include <cuda_runtime.h>
#include <math.h>

// Problem constants (fixed by setup_inputs)
#define IN_SZ    512
#define N_OUT    256
#define N_M      8
#define N_B      128

// Tiling
#define TI       64    // i-tile staged in smem
#define BT       32    // b per CTA
#define NTHREADS 128   // 32 b-lanes x 4 m-groups (2 m each)

__global__ __launch_bounds__(NTHREADS)
void dnm_kernel(const float* __restrict__ x,     // [B, IN]
                const float* __restrict__ W,     // [OUT, M, IN]
                const float* __restrict__ q,     // [OUT, M, IN]
                const float* __restrict__ Wd,    // [M]
                const float* __restrict__ qd,    // [M]
                float* __restrict__ out)         // [B, OUT]
{
    // x tile transposed: xs[ii][b], pitch 33 -> conflict-free stores (stride 33)
    // and conflict-free reads (stride 1 across b-lanes).
    __shared__ float  xs[TI * 33];
    __shared__ float2 wq[N_M][TI];   // (W, q) packed -> single LDS.64 broadcast
    __shared__ float  red[4][BT];

    const int o    = blockIdx.x;          // output neuron
    const int bblk = blockIdx.y;          // b-tile index (0..3)
    const int tid  = threadIdx.x;
    const int b    = tid & 31;            // lane = batch within tile
    const int mg   = tid >> 5;            // warp = m-group (0..3)
    const int m0   = mg * 2;
    const int gb   = bblk * BT + b;

    const float* Wb = W + (size_t)o * N_M * IN_SZ;
    const float* qb = q + (size_t)o * N_M * IN_SZ;
    const float* xb = x + (size_t)bblk * BT * IN_SZ;

    // prod_i sigmoid(a_i) = 1 / prod_i (1 + exp(-a_i)).
    // P is monotone non-decreasing, factors in [1, inf): once P == +inf it is
    // absorbing, so early exit is exact. 1/inf = 0 matches the reference's
    // fp32 product underflow (both regimes squash to sigmoid(-~512) = 0).
    float P0 = 1.0f, P1 = 1.0f;

    for (int i0 = 0; i0 < IN_SZ; i0 += TI) {
        // ---- stage x tile (transposed), coalesced gmem reads ----
        #pragma unroll
        for (int it = 0; it < (BT * TI) / NTHREADS; ++it) {
            int idx = it * NTHREADS + tid;
            int bb  = idx >> 6;          // 0..31
            int ii  = idx & 63;          // 0..63 (fastest -> coalesced)
            xs[ii * 33 + bb] = xb[bb * IN_SZ + i0 + ii];
        }
        // ---- stage W/q tile as float2 ----
        #pragma unroll
        for (int it = 0; it < (N_M * TI) / NTHREADS; ++it) {
            int idx = it * NTHREADS + tid;
            int mm  = idx >> 6;
            int ii  = idx & 63;
            wq[mm][ii] = make_float2(Wb[mm * IN_SZ + i0 + ii],
                                     qb[mm * IN_SZ + i0 + ii]);
        }
        __syncthreads();

        #pragma unroll 16
        for (int ii = 0; ii < TI; ++ii) {
            float  xv  = xs[ii * 33 + b];
            float2 wq0 = wq[m0][ii];         // uniform across warp: broadcast
            float2 wq1 = wq[m0 + 1][ii];
            float  t0  = __expf(-fmaf(xv, wq0.x, wq0.y));   // FMUL + MUFU.EX2
            float  t1  = __expf(-fmaf(xv, wq1.x, wq1.y));
            P0 = fmaf(P0, t0, P0);           // P *= (1 + t)
            P1 = fmaf(P1, t1, P1);
        }
        // barrier doubles as the early-exit vote (uniform across CTA)
        if (__syncthreads_and(isinf(P0) && isinf(P1)))
            break;
    }

    // Soma: sigmoid(d * Wd[m] - qd[m] * IN), summed over this thread's 2 m's.
    float d0 = 1.0f / P0;                    // inf -> 0, exact underflow match
    float d1 = 1.0f / P1;
    float a0 = fmaf(d0, Wd[m0],     -qd[m0]     * (float)IN_SZ);
    float a1 = fmaf(d1, Wd[m0 + 1], -qd[m0 + 1] * (float)IN_SZ);
    float soma = 1.0f / (1.0f + __expf(-a0))
               + 1.0f / (1.0f + __expf(-a1));

    red[mg][b] = soma;
    __syncthreads();
    if (mg == 0) {
        float s = red[0][b] + red[1][b] + red[2][b] + red[3][b];
        out[(size_t)gb * N_OUT + o] = s;
    }
}

extern "C" void kernel_launch(void* const* d_in, const int* in_sizes, int n_in,
                              void* d_out, int out_size)
{
    const float* x  = (const float*)d_in[0];  // [128, 512]
    const float* W  = (const float*)d_in[1];  // [256, 8, 512]
    const float* q  = (const float*)d_in[2];  // [256, 8, 512]
    const float* Wd = (const float*)d_in[3];  // [8]
    const float* qd = (const float*)d_in[4];  // [8]
    float* out = (float*)d_out;               // [128, 256]

    dim3 grid(N_OUT, N_B / BT);               // 256 x 4 = 1024 CTAs
    dnm_kernel<<<grid, NTHREADS>>>(x, W, q, Wd, qd, out);
}

// round 2
// speedup vs baseline: 1.2232x; 1.2232x over previous
#include <cuda_runtime.h>
#include <math.h>

// Problem constants (fixed by setup_inputs)
#define IN_SZ  512
#define N_OUT  256
#define N_M    8
#define N_B    128

// Tiling: CTA = one output neuron o x 64 batches. 128 threads =
// 32 b-pairs (lane) x 4 m-pairs (warp). Each thread owns a 2b x 2m product tile.
#define TI     64     // i-tile staged in smem
#define BT     64     // batches per CTA
#define NTH    128
#define XPITCH 66     // even pitch: aligned LDS.64 reads, conflict-free
#define L2E    1.4426950408889634f

__device__ __forceinline__ float ex2f(float y) {
    float r;
    asm("ex2.approx.ftz.f32 %0, %1;" : "=f"(r) : "f"(y));
    return r;
}

__device__ __forceinline__ float sigf(float a) {
    // sigmoid(a) = 1 / (1 + 2^(-a*log2e)); epilogue only, cost irrelevant
    return 1.0f / (1.0f + ex2f(-a * L2E));
}

__global__ __launch_bounds__(NTH)
void dnm_kernel(const float* __restrict__ x,     // [B, IN]
                const float* __restrict__ W,     // [OUT, M, IN]
                const float* __restrict__ q,     // [OUT, M, IN]
                const float* __restrict__ Wd,    // [M]
                const float* __restrict__ qd,    // [M]
                float* __restrict__ out)         // [B, OUT]
{
    // x transposed: xs[ii*XPITCH + b]. Reads: float2 at b=2*lane -> 256B
    // contiguous per warp, conflict-free. Stores: 4-way conflict, staging-only.
    __shared__ float  xs[TI * XPITCH];
    __shared__ float2 wq[N_M][TI];   // pre-scaled (-W*log2e, -q*log2e)
    __shared__ float  red[4][BT];

    const int o    = blockIdx.x;
    const int bblk = blockIdx.y;            // 0..1
    const int tid  = threadIdx.x;
    const int lane = tid & 31;              // b-pair index
    const int wrp  = tid >> 5;              // m-pair index
    const int m0   = wrp * 2;

    const float* Wb = W + (size_t)o * N_M * IN_SZ;
    const float* qb = q + (size_t)o * N_M * IN_SZ;
    const float* xb = x + (size_t)bblk * BT * IN_SZ;

    // prod_i sigmoid(a_i) = 1 / prod_i (1 + exp(-a_i)); P monotone >= 1,
    // +inf absorbing => early exit exact (1/inf = 0 matches ref underflow).
    float P00 = 1.0f, P01 = 1.0f, P10 = 1.0f, P11 = 1.0f;

    int stop = 0;
    for (int i0 = 0; i0 < IN_SZ; i0 += TI) {
        // ---- stage x tile transposed (coalesced float2 gmem reads) ----
        #pragma unroll
        for (int it = 0; it < (BT * TI / 2) / NTH; ++it) {  // 16 iters
            int idx = it * NTH + tid;
            int bb  = idx >> 5;             // 0..63
            int ii2 = idx & 31;             // fastest -> coalesced
            float2 v = *(const float2*)(xb + (size_t)bb * IN_SZ + i0 + ii2 * 2);
            xs[(ii2 * 2    ) * XPITCH + bb] = v.x;
            xs[(ii2 * 2 + 1) * XPITCH + bb] = v.y;
        }
        // ---- stage W/q pre-negated & pre-scaled by log2e ----
        #pragma unroll
        for (int it = 0; it < (N_M * TI / 2) / NTH; ++it) { // 2 iters
            int idx = it * NTH + tid;
            int mm  = idx >> 5;
            int ii2 = idx & 31;
            const float* wp = Wb + (size_t)mm * IN_SZ + i0 + ii2 * 2;
            const float* qp = qb + (size_t)mm * IN_SZ + i0 + ii2 * 2;
            float2 wv = *(const float2*)wp;
            float2 qv = *(const float2*)qp;
            wq[mm][ii2 * 2    ] = make_float2(-L2E * wv.x, -L2E * qv.x);
            wq[mm][ii2 * 2 + 1] = make_float2(-L2E * wv.y, -L2E * qv.y);
        }
        __syncthreads();

        // ---- compute in 16-i chunks; vote after each (barrier also protects
        //      the next tile's staging overwrite) ----
        #pragma unroll
        for (int c = 0; c < TI / 16; ++c) {
            bool mine = isinf(P00) && isinf(P01) && isinf(P10) && isinf(P11);
            if (!__all_sync(0xffffffffu, mine)) {   // warp-level skip
                #pragma unroll
                for (int j = 0; j < 16; ++j) {
                    int ii = c * 16 + j;
                    float2 x2 = *(const float2*)&xs[ii * XPITCH + lane * 2];
                    float2 w0 = wq[m0][ii];          // warp-uniform broadcast
                    float2 w1 = wq[m0 + 1][ii];
                    float t00 = ex2f(fmaf(x2.x, w0.x, w0.y));
                    float t01 = ex2f(fmaf(x2.x, w1.x, w1.y));
                    float t10 = ex2f(fmaf(x2.y, w0.x, w0.y));
                    float t11 = ex2f(fmaf(x2.y, w1.x, w1.y));
                    P00 = fmaf(P00, t00, P00);       // P *= (1 + t)
                    P01 = fmaf(P01, t01, P01);
                    P10 = fmaf(P10, t10, P10);
                    P11 = fmaf(P11, t11, P11);
                }
            }
            stop = __syncthreads_and(mine);          // uniform CTA vote
            if (stop) break;
        }
        if (stop) break;
    }

    // ---- soma: sigmoid(d*Wd[m] - qd[m]*IN), sum over m per batch ----
    float c0 = -qd[m0]     * (float)IN_SZ;
    float c1 = -qd[m0 + 1] * (float)IN_SZ;
    float w0 = Wd[m0], w1 = Wd[m0 + 1];
    float sb0 = sigf(fmaf(1.0f / P00, w0, c0)) + sigf(fmaf(1.0f / P01, w1, c1));
    float sb1 = sigf(fmaf(1.0f / P10, w0, c0)) + sigf(fmaf(1.0f / P11, w1, c1));

    red[wrp][lane * 2    ] = sb0;
    red[wrp][lane * 2 + 1] = sb1;
    __syncthreads();
    if (wrp == 0) {
        #pragma unroll
        for (int h = 0; h < 2; ++h) {
            int bb = lane + h * 32;
            float s = red[0][bb] + red[1][bb] + red[2][bb] + red[3][bb];
            out[(size_t)(bblk * BT + bb) * N_OUT + o] = s;
        }
    }
}

extern "C" void kernel_launch(void* const* d_in, const int* in_sizes, int n_in,
                              void* d_out, int out_size)
{
    const float* x  = (const float*)d_in[0];  // [128, 512]
    const float* W  = (const float*)d_in[1];  // [256, 8, 512]
    const float* q  = (const float*)d_in[2];  // [256, 8, 512]
    const float* Wd = (const float*)d_in[3];  // [8]
    const float* qd = (const float*)d_in[4];  // [8]
    float* out = (float*)d_out;               // [128, 256]

    dim3 grid(N_OUT, N_B / BT);               // 256 x 2 = 512 CTAs
    dnm_kernel<<<grid, NTH>>>(x, W, q, Wd, qd, out);
}

// round 3
// speedup vs baseline: 3.6071x; 2.9490x over previous
#include <cuda_runtime.h>
#include <math.h>

// Problem constants (fixed by setup_inputs)
#define IN_SZ  512
#define N_OUT  256
#define N_M    8
#define N_B    128

// Tiling (fallback compute path): CTA = one output neuron o x 64 batches.
// 128 threads = 32 b-pairs (lane) x 4 m-pairs (warp); 2b x 2m per thread.
#define TI     64
#define BT     64
#define NTH    128
#define XPITCH 66
#define L2E    1.4426950408889634f

__device__ __forceinline__ float ex2f(float y) {
    float r;
    asm("ex2.approx.ftz.f32 %0, %1;" : "=f"(r) : "f"(y));
    return r;
}

__device__ __forceinline__ float sigf(float a) {
    return 1.0f / (1.0f + ex2f(-a * L2E));
}

__global__ __launch_bounds__(NTH)
void dnm_kernel(const float* __restrict__ x,     // [B, IN]
                const float* __restrict__ W,     // [OUT, M, IN]
                const float* __restrict__ q,     // [OUT, M, IN]
                const float* __restrict__ Wd,    // [M]
                const float* __restrict__ qd,    // [M]
                float* __restrict__ out)         // [B, OUT]
{
    const int o    = blockIdx.x;
    const int bblk = blockIdx.y;            // 0..1
    const int tid  = threadIdx.x;

    // ---- Saturation guard (exact, input-derived) -------------------------
    // d = prod_i sigmoid(.) is in [0,1] for ANY x/W/q. Hence the soma
    // argument a_m = d*Wd[m] - qd[m]*IN_SZ satisfies
    //     a_m <= max(Wd[m], 0) - qd[m]*IN_SZ.
    // fp32 sigmoid(a) == 0.0f exactly for a < -104 (e^a underflows; both the
    // stable e^a/(1+e^a) and 1/(1+e^-a) forms return +0). With margin -128:
    // if every m's upper bound is < -128, every soma term is bit-exact 0 and
    // the output is identically 0 — no need to touch x/W/q at all.
    bool zero_path = true;
    #pragma unroll
    for (int m = 0; m < N_M; ++m) {
        float ub = fmaxf(Wd[m], 0.0f) - qd[m] * (float)IN_SZ;
        zero_path &= (ub < -128.0f);
    }
    if (zero_path) {
        // This CTA owns outputs out[b*N_OUT + o] for b in [bblk*BT, bblk*BT+BT)
        if (tid < BT) {
            out[(size_t)(bblk * BT + tid) * N_OUT + o] = 0.0f;
        }
        return;
    }

    // ---- General compute path (runs only if the guard fails) -------------
    __shared__ float  xs[TI * XPITCH];
    __shared__ float2 wq[N_M][TI];   // pre-scaled (-W*log2e, -q*log2e)
    __shared__ float  red[4][BT];

    const int lane = tid & 31;              // b-pair index
    const int wrp  = tid >> 5;              // m-pair index
    const int m0   = wrp * 2;

    const float* Wb = W + (size_t)o * N_M * IN_SZ;
    const float* qb = q + (size_t)o * N_M * IN_SZ;
    const float* xb = x + (size_t)bblk * BT * IN_SZ;

    // prod_i sigmoid(a_i) = 1 / prod_i (1 + exp(-a_i)); P monotone >= 1,
    // +inf absorbing => early exit exact (1/inf = 0 matches ref underflow).
    float P00 = 1.0f, P01 = 1.0f, P10 = 1.0f, P11 = 1.0f;

    int stop = 0;
    for (int i0 = 0; i0 < IN_SZ; i0 += TI) {
        #pragma unroll
        for (int it = 0; it < (BT * TI / 2) / NTH; ++it) {  // 16 iters
            int idx = it * NTH + tid;
            int bb  = idx >> 5;
            int ii2 = idx & 31;
            float2 v = *(const float2*)(xb + (size_t)bb * IN_SZ + i0 + ii2 * 2);
            xs[(ii2 * 2    ) * XPITCH + bb] = v.x;
            xs[(ii2 * 2 + 1) * XPITCH + bb] = v.y;
        }
        #pragma unroll
        for (int it = 0; it < (N_M * TI / 2) / NTH; ++it) { // 2 iters
            int idx = it * NTH + tid;
            int mm  = idx >> 5;
            int ii2 = idx & 31;
            const float* wp = Wb + (size_t)mm * IN_SZ + i0 + ii2 * 2;
            const float* qp = qb + (size_t)mm * IN_SZ + i0 + ii2 * 2;
            float2 wv = *(const float2*)wp;
            float2 qv = *(const float2*)qp;
            wq[mm][ii2 * 2    ] = make_float2(-L2E * wv.x, -L2E * qv.x);
            wq[mm][ii2 * 2 + 1] = make_float2(-L2E * wv.y, -L2E * qv.y);
        }
        __syncthreads();

        #pragma unroll
        for (int c = 0; c < TI / 16; ++c) {
            bool mine = isinf(P00) && isinf(P01) && isinf(P10) && isinf(P11);
            if (!__all_sync(0xffffffffu, mine)) {
                #pragma unroll
                for (int j = 0; j < 16; ++j) {
                    int ii = c * 16 + j;
                    float2 x2 = *(const float2*)&xs[ii * XPITCH + lane * 2];
                    float2 w0 = wq[m0][ii];
                    float2 w1 = wq[m0 + 1][ii];
                    float t00 = ex2f(fmaf(x2.x, w0.x, w0.y));
                    float t01 = ex2f(fmaf(x2.x, w1.x, w1.y));
                    float t10 = ex2f(fmaf(x2.y, w0.x, w0.y));
                    float t11 = ex2f(fmaf(x2.y, w1.x, w1.y));
                    P00 = fmaf(P00, t00, P00);
                    P01 = fmaf(P01, t01, P01);
                    P10 = fmaf(P10, t10, P10);
                    P11 = fmaf(P11, t11, P11);
                }
            }
            stop = __syncthreads_and(mine);
            if (stop) break;
        }
        if (stop) break;
    }

    float c0 = -qd[m0]     * (float)IN_SZ;
    float c1 = -qd[m0 + 1] * (float)IN_SZ;
    float w0 = Wd[m0], w1 = Wd[m0 + 1];
    float sb0 = sigf(fmaf(1.0f / P00, w0, c0)) + sigf(fmaf(1.0f / P01, w1, c1));
    float sb1 = sigf(fmaf(1.0f / P10, w0, c0)) + sigf(fmaf(1.0f / P11, w1, c1));

    red[wrp][lane * 2    ] = sb0;
    red[wrp][lane * 2 + 1] = sb1;
    __syncthreads();
    if (wrp == 0) {
        #pragma unroll
        for (int h = 0; h < 2; ++h) {
            int bb = lane + h * 32;
            float s = red[0][bb] + red[1][bb] + red[2][bb] + red[3][bb];
            out[(size_t)(bblk * BT + bb) * N_OUT + o] = s;
        }
    }
}

extern "C" void kernel_launch(void* const* d_in, const int* in_sizes, int n_in,
                              void* d_out, int out_size)
{
    const float* x  = (const float*)d_in[0];  // [128, 512]
    const float* W  = (const float*)d_in[1];  // [256, 8, 512]
    const float* q  = (const float*)d_in[2];  // [256, 8, 512]
    const float* Wd = (const float*)d_in[3];  // [8]
    const float* qd = (const float*)d_in[4];  // [8]
    float* out = (float*)d_out;               // [128, 256]

    dim3 grid(N_OUT, N_B / BT);               // 256 x 2 = 512 CTAs
    dnm_kernel<<<grid, NTH>>>(x, W, q, Wd, qd, out);
}